// round 5
// baseline (speedup 1.0000x reference)
#include <cuda_runtime.h>
#include <cuda_bf16.h>

// SingleLIFLayer: V <- V + (dt/tau)*(V_reset - V + I); spike = V >= V_th; reset.
// T=1024 sequential steps, N=65536 independent neurons.
// Pure streaming problem: 256 MB read + 256 MB write, DRAM-bound.
// Roofline floor ~67-77 us at ~7-8 TB/s effective HBM3e.

#ifndef LIF_T
#define LIF_T 1024
#endif
#ifndef LIF_N
#define LIF_N 65536
#endif

#define THREADS 128
#define TBATCH  16   // timesteps batched per iteration => MLP=16 per thread

__global__ __launch_bounds__(THREADS, 4)
void lif_kernel(const float* __restrict__ in, float* __restrict__ out) {
    const int n = blockIdx.x * THREADS + threadIdx.x;  // neuron index
    const float alpha = 0.05f;   // dt/tau = 1/20, exact in fp32
    const float vth   = 1.0f;

    float V = 0.0f;              // V_reset = 0

    const float* __restrict__ ip = in  + n;
    float*       __restrict__ sp = out + n;

    #pragma unroll 1
    for (int tb = 0; tb < LIF_T; tb += TBATCH) {
        // Phase 1: batch independent loads (front-batched -> deep MLP).
        float cur[TBATCH];
        #pragma unroll
        for (int k = 0; k < TBATCH; ++k) {
            cur[k] = __ldcs(ip + k * LIF_N);   // k*LIF_N <= 15*65536, fits int32
        }
        ip += TBATCH * LIF_N;

        // Phase 2: sequential LIF recurrence + spike decision.
        float spk[TBATCH];
        #pragma unroll
        for (int k = 0; k < TBATCH; ++k) {
            // V = V + alpha * (I - V); fma rounding immaterial:
            // |V| ~ 0.16 sigma vs threshold 1.0 (>6 sigma event margin)
            V = fmaf(alpha, cur[k] - V, V);
            bool s = (V >= vth);
            spk[k] = s ? 1.0f : 0.0f;
            if (s) V = 0.0f;
        }

        // Phase 3: batch streaming stores.
        #pragma unroll
        for (int k = 0; k < TBATCH; ++k) {
            __stcs(sp + k * LIF_N, spk[k]);
        }
        sp += TBATCH * LIF_N;
    }
}

extern "C" void kernel_launch(void* const* d_in, const int* in_sizes, int n_in,
                              void* d_out, int out_size) {
    const float* input = (const float*)d_in[0];
    float* spikes = (float*)d_out;

    const int grid = LIF_N / THREADS;  // 512 CTAs of 128 threads = 65536 threads
    lif_kernel<<<grid, THREADS>>>(input, spikes);
}